// round 14
// baseline (speedup 1.0000x reference)
#include <cuda_runtime.h>
#include <cuda_bf16.h>
#include <cstdint>

#define BB 64
#define HH 1024
#define SS 2048
#define LL 15

using bf16 = __nv_bfloat16;
typedef unsigned long long ull;

// ---------------- scratch (static device globals; no allocation) ------------
__device__ __align__(16) bf16 g_W1th[3*HH*HH], g_W1tl[3*HH*HH]; // [3072 n][1024 k]
__device__ __align__(16) bf16 g_W2th[HH*3*HH], g_W2tl[HH*3*HH]; // [1024 n][3072 k]
__device__ __align__(16) bf16 g_W3th[HH*HH],   g_W3tl[HH*HH];   // [1024][1024]
__device__ __align__(16) bf16 g_X1h[3*BB*HH],  g_X1l[3*BB*HH];  // [3 seg][64 b][1024 k]
__device__ __align__(16) bf16 g_X2h[BB*3*HH],  g_X2l[BB*3*HH];  // [64 b][3072 k]
__device__ __align__(16) bf16 g_X3h[BB*HH],    g_X3l[BB*HH];    // [64 b][1024 k]
__device__ __align__(16) float g_h2[BB*HH];                     // [64 b][1024 k]
__device__ __align__(16) float g_bcat[3*HH];
__device__ __align__(16) float g_P[16*3*HH*BB];                 // split-K partials [q][n][b]

// ---------------- PTX helpers ------------------------------------------------
__device__ __forceinline__ uint32_t smem_u32(const void* p) {
    uint32_t a;
    asm("{ .reg .u64 t; cvta.to.shared.u64 t, %1; cvt.u32.u64 %0, t; }" : "=r"(a) : "l"(p));
    return a;
}
__device__ __forceinline__ void cp16s(uint32_t saddr, const void* g) {
    asm volatile("cp.async.cg.shared.global [%0], [%1], 16;" :: "r"(saddr), "l"(g));
}
#define CP_COMMIT asm volatile("cp.async.commit_group;")
__device__ __forceinline__ void cp_wait_n(int n) {
    switch (n) {
        case 0: asm volatile("cp.async.wait_group 0;"); break;
        case 1: asm volatile("cp.async.wait_group 1;"); break;
        case 2: asm volatile("cp.async.wait_group 2;"); break;
        default: asm volatile("cp.async.wait_group 3;"); break;  // conservative for NT>4
    }
}
__device__ __forceinline__ void ldmat4(uint32_t (&r)[4], uint32_t addr) {
    asm volatile("ldmatrix.sync.aligned.m8n8.x4.shared.b16 {%0,%1,%2,%3}, [%4];"
                 : "=r"(r[0]), "=r"(r[1]), "=r"(r[2]), "=r"(r[3]) : "r"(addr));
}
__device__ __forceinline__ void mma16816(float (&d)[4], const uint32_t (&a)[4],
                                         uint32_t b0, uint32_t b1) {
    asm volatile("mma.sync.aligned.m16n8k16.row.col.f32.bf16.bf16.f32 "
                 "{%0,%1,%2,%3}, {%4,%5,%6,%7}, {%8,%9}, {%0,%1,%2,%3};"
                 : "+f"(d[0]), "+f"(d[1]), "+f"(d[2]), "+f"(d[3])
                 : "r"(a[0]), "r"(a[1]), "r"(a[2]), "r"(a[3]), "r"(b0), "r"(b1));
}

// ---------------- prep: span means + tanh + bf16 split ----------------------
__global__ void prep_kernel(const float* __restrict__ x,
                            const int* __restrict__ eidx,
                            const float* __restrict__ b_cls,
                            const float* __restrict__ b_e1,
                            const float* __restrict__ b_e2) {
    int b = blockIdx.x;
    int tid = threadIdx.x;  // 256
    int h = blockIdx.y * 256 + tid;

    if (blockIdx.y == 0 && b < 12) {
        int gidx = b * 256 + tid;
        if (gidx < HH)          g_bcat[gidx] = b_cls[gidx];
        else if (gidx < 2 * HH) g_bcat[gidx] = b_e1[gidx - HH];
        else                    g_bcat[gidx] = b_e2[gidx - 2 * HH];
    }

    int s1 = eidx[b * 4 + 0], e1 = eidx[b * 4 + 1];
    int s2 = eidx[b * 4 + 2], e2 = eidx[b * 4 + 3];
    float c1 = 1.0f / (float)max(e1 - s1, 1);
    float c2 = 1.0f / (float)max(e2 - s2, 1);
    const float* xb = x + (size_t)b * SS * HH;

    float a1 = 0.f;
#pragma unroll 4
    for (int p = s1; p < e1; ++p) a1 += xb[(size_t)p * HH + h];
    float a2 = 0.f;
#pragma unroll 4
    for (int p = s2; p < e2; ++p) a2 += xb[(size_t)p * HH + h];
    float v[3] = { tanhf(xb[h]), tanhf(a1 * c1), tanhf(a2 * c2) };
#pragma unroll
    for (int s = 0; s < 3; s++) {
        size_t idx = ((size_t)(s * BB + b)) * HH + h;
        bf16 hv = __float2bfloat16(v[s]);
        bf16 lv = __float2bfloat16(v[s] - __bfloat162float(hv));
        g_X1h[idx] = hv;
        g_X1l[idx] = lv;
    }
}

// ---------------- fused weight transpose + bf16 hi/lo split ------------------
__global__ __launch_bounds__(256)
void convAll(const float* __restrict__ Wc,  const float* __restrict__ We1,
             const float* __restrict__ We2, const float* __restrict__ W1,
             const float* __restrict__ W2) {
    __shared__ float S[64][65];
    int bid = blockIdx.x;
    const float* src; bf16 *Th, *Tl; int Ks; int base;
    if (bid < 256)       { src = Wc;  Th = g_W1th;                   Tl = g_W1tl;                   Ks = HH;   base = 0; }
    else if (bid < 512)  { src = We1; Th = g_W1th + (size_t)HH*HH;   Tl = g_W1tl + (size_t)HH*HH;   Ks = HH;   base = 256; }
    else if (bid < 768)  { src = We2; Th = g_W1th + (size_t)2*HH*HH; Tl = g_W1tl + (size_t)2*HH*HH; Ks = HH;   base = 512; }
    else if (bid < 1536) { src = W1;  Th = g_W2th;                   Tl = g_W2tl;                   Ks = 3*HH; base = 768; }
    else                 { src = W2;  Th = g_W3th;                   Tl = g_W3tl;                   Ks = HH;   base = 1536; }
    int tw = bid - base;
    int kt = tw >> 4, nt = tw & 15;
    int k0 = kt * 64, n0 = nt * 64;
    int t = threadIdx.x;

    int lr = t >> 4, lc = (t & 15) * 4;
#pragma unroll
    for (int i = 0; i < 4; i++) {
        float4 v = *(const float4*)(src + (size_t)(k0 + lr + 16 * i) * HH + n0 + lc);
        S[lr + 16 * i][lc + 0] = v.x; S[lr + 16 * i][lc + 1] = v.y;
        S[lr + 16 * i][lc + 2] = v.z; S[lr + 16 * i][lc + 3] = v.w;
    }
    __syncthreads();

    int k8 = (t & 7) * 8;
#pragma unroll
    for (int ii = 0; ii < 2; ii++) {
        int nl = (t >> 3) + 32 * ii;
        __nv_bfloat162 hh[4], ll[4];
#pragma unroll
        for (int j = 0; j < 4; j++) {
            float v0 = S[k8 + 2 * j][nl], v1 = S[k8 + 2 * j + 1][nl];
            bf16 h0 = __float2bfloat16(v0), h1 = __float2bfloat16(v1);
            hh[j] = __nv_bfloat162(h0, h1);
            ll[j] = __nv_bfloat162(__float2bfloat16(v0 - __bfloat162float(h0)),
                                   __float2bfloat16(v1 - __bfloat162float(h1)));
        }
        size_t o = (size_t)(n0 + nl) * Ks + k0 + k8;
        *(uint4*)&Th[o] = *(uint4*)hh;
        *(uint4*)&Tl[o] = *(uint4*)ll;
    }
}

// ---------------- HMMA split-K GEMM (mma.sync m16n8k16 bf16, 2-split) --------
template<int NT>
__global__ __launch_bounds__(128)
void gemm_mma(int wsel, int nseg, int Kt, int Ntot) {
    extern __shared__ char smem[];
    constexpr int WSLAB = 128 * 80;   // 10240 B
    constexpr int XSLAB = 64 * 80;    // 5120 B
    const int WHo = 0;
    const int WLo = NT * WSLAB;
    const int XHo = 2 * NT * WSLAB;
    const int XLo = XHo + NT * XSLAB;
    uint32_t sb = smem_u32(smem);

    int tid = threadIdx.x, w = tid >> 5, lane = tid & 31;
    int n0 = blockIdx.x * 128;
    int kbeg = blockIdx.y * (NT * 32);

    const bf16 *Whp, *Wlp, *Xhp, *Xlp;
    if (wsel == 0)      { Whp = g_W1th; Wlp = g_W1tl; Xhp = g_X1h; Xlp = g_X1l; }
    else if (wsel == 1) { Whp = g_W2th; Wlp = g_W2tl; Xhp = g_X2h; Xlp = g_X2l; }
    else                { Whp = g_W3th; Wlp = g_W3tl; Xhp = g_X3h; Xlp = g_X3l; }
    if (nseg) {
        size_t xoff = (size_t)(n0 / nseg) * BB * Kt;
        Xhp += xoff; Xlp += xoff;
    }

    // --- prologue: stage all NT slabs, one commit group each ---
#pragma unroll
    for (int tt = 0; tt < NT; tt++) {
        int k0 = kbeg + tt * 32;
#pragma unroll
        for (int i = 0; i < 4; i++) {          // W: 128 rows x 4 chunks
            int q = tid + 128 * i;
            int r = q >> 2, c = q & 3;
            uint32_t doff = (uint32_t)(r * 80 + c * 16);
            const size_t so = (size_t)(n0 + r) * Kt + k0 + c * 8;
            cp16s(sb + WHo + tt * WSLAB + doff, Whp + so);
            cp16s(sb + WLo + tt * WSLAB + doff, Wlp + so);
        }
#pragma unroll
        for (int i = 0; i < 2; i++) {          // X: 64 rows x 4 chunks
            int q = tid + 128 * i;
            int r = q >> 2, c = q & 3;
            uint32_t doff = (uint32_t)(r * 80 + c * 16);
            const size_t so = (size_t)r * Kt + k0 + c * 8;
            cp16s(sb + XHo + tt * XSLAB + doff, Xhp + so);
            cp16s(sb + XLo + tt * XSLAB + doff, Xlp + so);
        }
        CP_COMMIT;
    }

    float d[2][8][4] = {};

    int rowA = (lane & 7) + ((lane >> 3) & 1) * 8;
    int cA = lane >> 4;
    uint32_t pA = (uint32_t)((w * 32 + rowA) * 80 + cA * 16);
    int rowX = (lane & 7) + (lane >> 4) * 8;
    int cX = (lane >> 3) & 1;
    uint32_t pB = (uint32_t)(rowX * 80 + cX * 16);

#pragma unroll
    for (int tt = 0; tt < NT; tt++) {
        cp_wait_n(NT - 1 - tt);
        __syncthreads();

#pragma unroll
        for (int s = 0; s < 2; s++) {          // two k16 steps per BK=32 slab
            uint32_t ko = s * 32;
            uint32_t ah[2][4], al[2][4];
            ldmat4(ah[0], sb + WHo + tt * WSLAB + pA + ko);
            ldmat4(ah[1], sb + WHo + tt * WSLAB + pA + ko + 16 * 80);
            ldmat4(al[0], sb + WLo + tt * WSLAB + pA + ko);
            ldmat4(al[1], sb + WLo + tt * WSLAB + pA + ko + 16 * 80);
            uint32_t bh[4][4], bl[4][4];
#pragma unroll
            for (int p = 0; p < 4; p++) {
                ldmat4(bh[p], sb + XHo + tt * XSLAB + pB + ko + p * 16 * 80);
                ldmat4(bl[p], sb + XLo + tt * XSLAB + pB + ko + p * 16 * 80);
            }
#pragma unroll
            for (int mt = 0; mt < 2; mt++)
#pragma unroll
                for (int nt = 0; nt < 8; nt++) {
                    int p = nt >> 1, hf = (nt & 1) * 2;
                    mma16816(d[mt][nt], ah[mt], bh[p][hf], bh[p][hf + 1]);
                    mma16816(d[mt][nt], ah[mt], bl[p][hf], bl[p][hf + 1]);
                    mma16816(d[mt][nt], al[mt], bh[p][hf], bh[p][hf + 1]);
                }
        }
    }

    // --- epilogue: P[(q*Ntot + n)*64 + b] ---
    float* pq = g_P + (size_t)blockIdx.y * Ntot * BB;
#pragma unroll
    for (int mt = 0; mt < 2; mt++)
#pragma unroll
        for (int nt = 0; nt < 8; nt++) {
            int n = n0 + w * 32 + mt * 16 + (lane >> 2);
            int b = nt * 8 + (lane & 3) * 2;
            *(float2*)&pq[(size_t)n * BB + b]       = make_float2(d[mt][nt][0], d[mt][nt][1]);
            *(float2*)&pq[(size_t)(n + 8) * BB + b] = make_float2(d[mt][nt][2], d[mt][nt][3]);
        }
}

// ---------------- transposing reduce, high-parallelism -----------------------
// 8 n-rows per block, 512 threads: one (n,b) element per thread in load phase.
// ysel 0: -> g_X2 (bf16 hi/lo, bias=g_bcat), 1: -> g_X3, 2: -> g_h2 fp32
template<int KS>
__global__ __launch_bounds__(512)
void reduceT(const float* __restrict__ bias, int ysel, int Ntot) {
    __shared__ float S[8][65];
    int n0 = blockIdx.x * 8;
    int t = threadIdx.x;          // 512
    int nl = t >> 6, b = t & 63;
    int n = n0 + nl;
    const float* p = g_P + (size_t)n * BB + b;
    float acc[KS];
#pragma unroll
    for (int q = 0; q < KS; q++) acc[q] = p[(size_t)q * Ntot * BB];
    float s = acc[0];
#pragma unroll
    for (int q = 1; q < KS; q++) s += acc[q];
    s += (ysel == 0) ? g_bcat[n] : bias[n];
    S[nl][b] = s;
    __syncthreads();

    int tt = t & 255;
    int wb = tt >> 2, np = (tt & 3) * 2;
    float v0 = S[np][wb], v1 = S[np + 1][wb];
    size_t o = (size_t)wb * Ntot + n0 + np;
    if (ysel == 2) {
        if (t < 256) *(float2*)&g_h2[o] = make_float2(v0, v1);
    } else {
        bf16 h0 = __float2bfloat16(v0), h1 = __float2bfloat16(v1);
        if (t < 256) {
            bf16* Yh = (ysel == 0) ? g_X2h : g_X3h;
            *(__nv_bfloat162*)&Yh[o] = __nv_bfloat162(h0, h1);
        } else {
            bf16* Yl = (ysel == 0) ? g_X2l : g_X3l;
            *(__nv_bfloat162*)&Yl[o] = __nv_bfloat162(
                __float2bfloat16(v0 - __bfloat162float(h0)),
                __float2bfloat16(v1 - __bfloat162float(h1)));
        }
    }
}

// ---------------- output GEMM: one block per batch row ----------------------
// h2[b][k] x Wout[k][15]: Wout rows are 60B contiguous -> L2-friendly.
__global__ __launch_bounds__(128)
void out_gemm(const float* __restrict__ Wout,
              const float* __restrict__ bout,
              float* __restrict__ out) {
    int b = blockIdx.x;   // 0..63
    int t = threadIdx.x;  // 128
    float acc[LL];
#pragma unroll
    for (int l = 0; l < LL; l++) acc[l] = 0.f;
    for (int k = t; k < HH; k += 128) {
        float h = g_h2[(size_t)b * HH + k];
        const float* wr = Wout + (size_t)k * LL;
#pragma unroll
        for (int l = 0; l < LL; l++) acc[l] += h * wr[l];
    }
    __shared__ float S[128][16];
#pragma unroll
    for (int l = 0; l < LL; l++) S[t][l] = acc[l];
    __syncthreads();
    if (t < LL) {
        float s = bout[t];
#pragma unroll 8
        for (int i = 0; i < 128; i++) s += S[i][t];
        out[b * LL + t] = s;
    }
}

// ---------------- launch ------------------------------------------------------
extern "C" void kernel_launch(void* const* d_in, const int* in_sizes, int n_in,
                              void* d_out, int out_size) {
    const float* x      = (const float*)d_in[0];
    const int*   eidx   = (const int*)d_in[1];
    const float* W_cls  = (const float*)d_in[2];
    const float* b_cls  = (const float*)d_in[3];
    const float* W_e1   = (const float*)d_in[4];
    const float* b_e1   = (const float*)d_in[5];
    const float* W_e2   = (const float*)d_in[6];
    const float* b_e2   = (const float*)d_in[7];
    const float* W1     = (const float*)d_in[8];
    const float* b1     = (const float*)d_in[9];
    const float* W2     = (const float*)d_in[10];
    const float* b2     = (const float*)d_in[11];
    const float* Wout   = (const float*)d_in[12];
    const float* bout   = (const float*)d_in[13];
    float* out = (float*)d_out;

    const int SLAB = 2 * 128 * 80 + 2 * 64 * 80;   // 30720 B per K=32 slab
    cudaFuncSetAttribute(gemm_mma<4>, cudaFuncAttributeMaxDynamicSharedMemorySize,
                         4 * SLAB);                // 122880
    cudaFuncSetAttribute(gemm_mma<6>, cudaFuncAttributeMaxDynamicSharedMemorySize,
                         6 * SLAB);                // 184320

    // 1) prep + fused weight conversion
    prep_kernel<<<dim3(BB, HH / 256), 256>>>(x, eidx, b_cls, b_e1, b_e2);
    convAll<<<1792, 256>>>(W_cls, W_e1, W_e2, W1, W2);

    // 2) GEMM1: block-diag weights (24 x 8 CTAs, K=128/CTA)
    gemm_mma<4><<<dim3(24, 8), 128, 4 * SLAB>>>(0, HH, HH, 3 * HH);
    reduceT<8><<<3 * HH / 8, 512>>>(nullptr, 0, 3 * HH);

    // 3) GEMM2: W1^T x H3 (8 x 16 CTAs, K=192/CTA)
    gemm_mma<6><<<dim3(8, 16), 128, 6 * SLAB>>>(1, 0, 3 * HH, HH);
    reduceT<16><<<HH / 8, 512>>>(b1, 1, HH);

    // 4) GEMM3: W2^T x h1 (8 x 8 CTAs, K=128/CTA)
    gemm_mma<4><<<dim3(8, 8), 128, 4 * SLAB>>>(2, 0, HH, HH);
    reduceT<8><<<HH / 8, 512>>>(b2, 2, HH);

    // 5) output projection
    out_gemm<<<BB, 128>>>(Wout, bout, out);

    (void)in_sizes; (void)n_in; (void)out_size;
}